// round 7
// baseline (speedup 1.0000x reference)
#include <cuda_runtime.h>
#include <cstdint>

// COMPLEXES=2048, RESY=RESX=16, FEAT=64, P=256
// map: [C,16,16,64] f32 ; u,v: [C,256] f32 ; out: [C,256,64] f32
//
// Work item = (complex, feature-quarter). 8192 items. Tile per item =
// 16x16x16 f32 = 16 KB, double-buffered. 6 CTAs/SM for deep phase stagger.

constexpr int C_    = 2048;
constexpr int H_    = 16;
constexpr int W_    = 16;
constexpr int F_    = 64;
constexpr int FQ_   = 16;                       // features per quarter
constexpr int P_    = 256;
constexpr int ITEMS = C_ * 4;                   // 8192
constexpr int QT_FLOATS = H_ * W_ * FQ_;        // 4096 floats = 16 KB
constexpr int QT_BYTES  = QT_FLOATS * 4;
constexpr int QT_CHUNKS = QT_FLOATS / 4;        // 1024 x 16B
constexpr int THREADS   = 256;
constexpr int GRID      = 148 * 6;              // 888 persistent CTAs

// Dyn smem: 2 x 16KB tiles + fx/fy [2][256] f32 + off [2][256] u16 = 37888 B
// -> 6 CTAs/SM (227 KB), 48 warps/SM.
constexpr int SMEM_TOTAL = 2 * QT_BYTES + 2 * P_ * 4 * 2 + 2 * P_ * 2;

__device__ __forceinline__ void cp_async16(uint32_t smem_addr, const void* gptr) {
    asm volatile("cp.async.cg.shared.global [%0], [%1], 16;\n"
                 :: "r"(smem_addr), "l"(gptr) : "memory");
}
__device__ __forceinline__ void cp_async_commit() {
    asm volatile("cp.async.commit_group;\n" ::: "memory");
}
__device__ __forceinline__ void cp_async_wait1() {
    asm volatile("cp.async.wait_group 1;\n" ::: "memory");
}

__global__ __launch_bounds__(THREADS)
void ngf_texture_fetch_kernel(const float* __restrict__ gmap,
                              const float* __restrict__ gu,
                              const float* __restrict__ gv,
                              float* __restrict__ gout)
{
    extern __shared__ __align__(16) float smem[];
    float*    tiles = smem;                                   // [2][4096]
    float*    s_fx  = smem + 2 * QT_FLOATS;                   // [2][256]
    float*    s_fy  = s_fx + 2 * P_;                          // [2][256]
    uint16_t* s_off = (uint16_t*)(s_fy + 2 * P_);             // [2][256]

    const int t   = threadIdx.x;
    const int bid = blockIdx.x;

    const uint32_t tile_sm0 =
        (uint32_t)__cvta_generic_to_shared(tiles) + t * 16u;

    const int fq = (t & 3);           // feature quad 0..3 (4 floats each)
    const int sl = (t >> 2);          // sample lane 0..63

    // ---- stage item w into buffer b (cp.async, no reg round-trip) ----
    auto stage = [&](int w, int b) {
        const int c = w >> 2;
        const int q = w & 3;
        const float4* base4 = (const float4*)(gmap + (size_t)c * (H_ * W_ * F_));
        const uint32_t dst0 = tile_sm0 + (uint32_t)b * QT_BYTES;
        #pragma unroll
        for (int k = 0; k < QT_CHUNKS / THREADS; ++k) {        // 4
            const int j    = k * THREADS + t;
            const int cell = j >> 2;                           // 0..255
            const int wi   = j & 3;                            // float4 in quarter
            cp_async16(dst0 + k * (THREADS * 16u),
                       base4 + cell * (F_ / 4) + q * (FQ_ / 4) + wi);
        }
    };

    auto params = [&](int w, int b) {
        const int c = w >> 2;
        const float uu = gu[(size_t)c * P_ + t];
        const float vv = gv[(size_t)c * P_ + t];
        const float x = uu * (float)(W_ - 1);
        const float y = vv * (float)(H_ - 1);
        int x0 = (int)floorf(x);
        int y0 = (int)floorf(y);
        x0 = min(max(x0, 0), W_ - 2);
        y0 = min(max(y0, 0), H_ - 2);
        s_fx[b * P_ + t]  = x - (float)x0;
        s_fy[b * P_ + t]  = y - (float)y0;
        s_off[b * P_ + t] = (uint16_t)((y0 * W_ + x0) * FQ_);
    };

    // ---- prologue: first item into buffer 0 ----
    {
        stage(bid, 0);                 // bid < 888 < 8192, always valid
        cp_async_commit();
        params(bid, 0);
    }

    // ---- persistent loop ----
    int b = 0;
    for (int w = bid; w < ITEMS; w += GRID, b ^= 1) {
        // 1) stage next item into the other buffer (overlaps this compute)
        const int wn = w + GRID;
        if (wn < ITEMS) {
            stage(wn, b ^ 1);
            params(wn, b ^ 1);
        }
        cp_async_commit();             // one group per iteration, always

        // 2) current tile has landed (non-blocking in steady state)
        cp_async_wait1();
        __syncthreads();

        // 3) bilinear gather + coalesced float4 stores
        const int c = w >> 2;
        const int q = w & 3;
        const float*    tile = tiles + b * QT_FLOATS;
        const uint16_t* off_ = s_off + b * P_;
        const float*    fx_  = s_fx + b * P_;
        const float*    fy_  = s_fy + b * P_;
        float4* out4 = (float4*)(gout + (size_t)c * P_ * F_) + q * (FQ_ / 4);

        #pragma unroll
        for (int i = 0; i < P_ / 64; ++i) {            // 4 iterations
            const int s   = i * 64 + sl;
            const int off = (int)off_[s] + fq * 4;
            const float fx = fx_[s];
            const float fy = fy_[s];

            const float4 g00 = *(const float4*)(tile + off);
            const float4 g01 = *(const float4*)(tile + off + FQ_);
            const float4 g10 = *(const float4*)(tile + off + W_ * FQ_);
            const float4 g11 = *(const float4*)(tile + off + W_ * FQ_ + FQ_);

            const float w11 = fx * fy;
            const float w01 = fx - w11;               // fx*(1-fy)
            const float w10 = fy - w11;               // (1-fx)*fy
            const float w00 = 1.0f - fx - fy + w11;

            float4 r;
            r.x = g00.x * w00 + g01.x * w01 + g10.x * w10 + g11.x * w11;
            r.y = g00.y * w00 + g01.y * w01 + g10.y * w10 + g11.y * w11;
            r.z = g00.z * w00 + g01.z * w01 + g10.z * w10 + g11.z * w11;
            r.w = g00.w * w00 + g01.w * w01 + g10.w * w10 + g11.w * w11;

            out4[s * (F_ / 4) + fq] = r;
        }

        // 4) all reads of tile[b]/params[b] done before next iter overwrites
        __syncthreads();
    }
}

extern "C" void kernel_launch(void* const* d_in, const int* in_sizes, int n_in,
                              void* d_out, int out_size)
{
    const float* gmap = (const float*)d_in[0];
    const float* gu   = (const float*)d_in[1];
    const float* gv   = (const float*)d_in[2];
    float* gout       = (float*)d_out;

    cudaFuncSetAttribute(ngf_texture_fetch_kernel,
                         cudaFuncAttributeMaxDynamicSharedMemorySize, SMEM_TOTAL);

    ngf_texture_fetch_kernel<<<GRID, THREADS, SMEM_TOTAL>>>(gmap, gu, gv, gout);
}

// round 9
// speedup vs baseline: 1.4192x; 1.4192x over previous
#include <cuda_runtime.h>
#include <cstdint>

// COMPLEXES=2048, RESY=RESX=16, FEAT=64, P=256
// map: [C,16,16,64] f32 ; u,v: [C,256] f32 ; out: [C,256,64] f32
//
// Work item = (complex, feature-half FH=32). 4096 items, 32 KB tile each.
// Single-buffer, 6 CTAs/SM stagger, atomic work stealing, L2 prefetch ahead.

constexpr int C_    = 2048;
constexpr int H_    = 16;
constexpr int W_    = 16;
constexpr int F_    = 64;
constexpr int FH_   = 32;                       // features per half (128B rows)
constexpr int P_    = 256;
constexpr int ITEMS = C_ * 2;                   // 4096
constexpr int HALF_FLOATS = H_ * W_ * FH_;      // 8192 floats = 32 KB
constexpr int HALF_BYTES  = HALF_FLOATS * 4;
constexpr int HALF_CHUNKS = HALF_FLOATS / 4;    // 2048 x 16B
constexpr int THREADS     = 256;
constexpr int GRID        = 148 * 6;            // 888 persistent CTAs

// Dyn smem: tile 32768 + fx/fy 2048 + off(u16) 512 + next 16 = 35344 B
// -> 6 CTAs/SM (212 KB of 227 KB), 48 warps/SM.
constexpr int SMEM_TOTAL = HALF_BYTES + P_ * 4 * 2 + P_ * 2 + 16;

__device__ unsigned int g_ctr;

__global__ void reset_ctr_kernel() { g_ctr = GRID; }

__device__ __forceinline__ void cp_async16(uint32_t smem_addr, const void* gptr) {
    asm volatile("cp.async.cg.shared.global [%0], [%1], 16;\n"
                 :: "r"(smem_addr), "l"(gptr) : "memory");
}
__device__ __forceinline__ void cp_async_commit() {
    asm volatile("cp.async.commit_group;\n" ::: "memory");
}
__device__ __forceinline__ void cp_async_wait0() {
    asm volatile("cp.async.wait_group 0;\n" ::: "memory");
}
__device__ __forceinline__ void l2_prefetch_bulk(const void* gptr, uint32_t bytes) {
    asm volatile("cp.async.bulk.prefetch.L2.global [%0], %1;\n"
                 :: "l"(gptr), "r"(bytes) : "memory");
}

__global__ __launch_bounds__(THREADS)
void ngf_texture_fetch_kernel(const float* __restrict__ gmap,
                              const float* __restrict__ gu,
                              const float* __restrict__ gv,
                              float* __restrict__ gout)
{
    extern __shared__ __align__(16) float smem[];
    float*    tile   = smem;                               // 8192 floats
    float*    s_fx   = smem + HALF_FLOATS;                 // 256
    float*    s_fy   = s_fx + P_;                          // 256
    uint16_t* s_off  = (uint16_t*)(s_fy + P_);             // 256
    int*      s_next = (int*)(s_off + P_);                 // 1

    const int t   = threadIdx.x;
    const int bid = blockIdx.x;

    const uint32_t tile_sm =
        (uint32_t)__cvta_generic_to_shared(tile) + t * 16u;

    const int fq = (t & 7);           // feature quad 0..7 (4 floats)
    const int sl = (t >> 3);          // sample lane 0..31

    int w = bid;                      // first item statically assigned
    while (w < ITEMS) {
        // 0) steal the next item + L2-prefetch its complex (one phase ahead)
        if (t == 0) {
            unsigned int wn = atomicAdd(&g_ctr, 1u);
            *s_next = (int)wn;
            if (wn < (unsigned)ITEMS) {
                l2_prefetch_bulk(gmap + (size_t)(wn >> 1) * (H_ * W_ * F_),
                                 (uint32_t)(H_ * W_ * F_ * 4));   // 64 KB
            }
        }

        const int c = w >> 1;
        const int h = w & 1;

        // 1) stage this item's 32KB tile via cp.async (L1-bypass)
        {
            const float4* base4 = (const float4*)(gmap + (size_t)c * (H_ * W_ * F_));
            #pragma unroll
            for (int k = 0; k < HALF_CHUNKS / THREADS; ++k) {    // 8
                const int j    = k * THREADS + t;
                const int cell = j >> 3;
                const int wi   = j & 7;
                cp_async16(tile_sm + k * (THREADS * 16u),
                           base4 + cell * (F_ / 4) + h * (FH_ / 4) + wi);
            }
            cp_async_commit();
        }

        // 2) per-sample params while the tile streams in
        {
            const float uu = gu[(size_t)c * P_ + t];
            const float vv = gv[(size_t)c * P_ + t];
            const float x = uu * (float)(W_ - 1);
            const float y = vv * (float)(H_ - 1);
            int x0 = (int)floorf(x);
            int y0 = (int)floorf(y);
            x0 = min(max(x0, 0), W_ - 2);
            y0 = min(max(y0, 0), H_ - 2);
            s_fx[t]  = x - (float)x0;
            s_fy[t]  = y - (float)y0;
            s_off[t] = (uint16_t)((y0 * W_ + x0) * FH_);
        }

        // 3) wait for tile, publish params + stolen index
        cp_async_wait0();
        __syncthreads();

        const int wn = *s_next;       // written before the barrier

        // 4) bilinear gather (conflict-free 128B rows) + coalesced stores
        float4* out4 = (float4*)(gout + (size_t)c * P_ * F_);
        #pragma unroll
        for (int i = 0; i < P_ / 32; ++i) {            // 8 iterations
            const int s   = i * 32 + sl;
            const int off = (int)s_off[s] + fq * 4;
            const float fx = s_fx[s];
            const float fy = s_fy[s];

            const float4 g00 = *(const float4*)(tile + off);
            const float4 g01 = *(const float4*)(tile + off + FH_);
            const float4 g10 = *(const float4*)(tile + off + W_ * FH_);
            const float4 g11 = *(const float4*)(tile + off + W_ * FH_ + FH_);

            const float w11 = fx * fy;
            const float w01 = fx - w11;               // fx*(1-fy)
            const float w10 = fy - w11;               // (1-fx)*fy
            const float w00 = 1.0f - fx - fy + w11;

            float4 r;
            r.x = g00.x * w00 + g01.x * w01 + g10.x * w10 + g11.x * w11;
            r.y = g00.y * w00 + g01.y * w01 + g10.y * w10 + g11.y * w11;
            r.z = g00.z * w00 + g01.z * w01 + g10.z * w10 + g11.z * w11;
            r.w = g00.w * w00 + g01.w * w01 + g10.w * w10 + g11.w * w11;

            out4[s * (F_ / 4) + h * (FH_ / 4) + fq] = r;
        }

        // 5) all reads of tile/params/s_next done before next item overwrites
        __syncthreads();
        w = wn;
    }
}

extern "C" void kernel_launch(void* const* d_in, const int* in_sizes, int n_in,
                              void* d_out, int out_size)
{
    const float* gmap = (const float*)d_in[0];
    const float* gu   = (const float*)d_in[1];
    const float* gv   = (const float*)d_in[2];
    float* gout       = (float*)d_out;

    cudaFuncSetAttribute(ngf_texture_fetch_kernel,
                         cudaFuncAttributeMaxDynamicSharedMemorySize, SMEM_TOTAL);

    reset_ctr_kernel<<<1, 1>>>();
    ngf_texture_fetch_kernel<<<GRID, THREADS, SMEM_TOTAL>>>(gmap, gu, gv, gout);
}

// round 10
// speedup vs baseline: 1.6398x; 1.1554x over previous
#include <cuda_runtime.h>
#include <cstdint>

// COMPLEXES=2048, RESY=RESX=16, FEAT=64, P=256
// map: [C,16,16,64] f32 ; u,v: [C,256] f32 ; out: [C,256,64] f32
//
// Work item = (complex, feature-half FH=32). 4096 items, 32 KB tile each,
// DOUBLE-buffered (R6 mechanism) + atomic work stealing (kills ragged tail)
// + non-temporal output stores (keep L2 for the read stream).

constexpr int C_    = 2048;
constexpr int H_    = 16;
constexpr int W_    = 16;
constexpr int F_    = 64;
constexpr int FH_   = 32;                      // features per half (128B rows)
constexpr int P_    = 256;
constexpr int ITEMS = C_ * 2;                  // 4096
constexpr int HALF_FLOATS = H_ * W_ * FH_;     // 8192 floats = 32 KB
constexpr int HALF_CHUNKS = HALF_FLOATS / 4;   // 2048 x 16B
constexpr int THREADS     = 256;
constexpr int GRID        = 148 * 3;           // 444 persistent CTAs

// Dyn smem: 2 x 32KB tiles + 2 x (fx/fy f32 + off u16)[256] + s_next[2]
constexpr int SMEM_TOTAL = 2 * HALF_FLOATS * 4        // 65536
                         + 2 * P_ * 4 * 2             // fx, fy
                         + 2 * P_ * 2                 // off (u16)
                         + 16;                        // s_next + pad

__device__ unsigned int g_ctr;
__global__ void reset_ctr_kernel() { g_ctr = GRID; }

__device__ __forceinline__ void cp_async16(uint32_t smem_addr, const void* gptr) {
    asm volatile("cp.async.cg.shared.global [%0], [%1], 16;\n"
                 :: "r"(smem_addr), "l"(gptr) : "memory");
}
__device__ __forceinline__ void cp_async_commit() {
    asm volatile("cp.async.commit_group;\n" ::: "memory");
}
__device__ __forceinline__ void cp_async_wait1() {
    asm volatile("cp.async.wait_group 1;\n" ::: "memory");
}

__global__ __launch_bounds__(THREADS)
void ngf_texture_fetch_kernel(const float* __restrict__ gmap,
                              const float* __restrict__ gu,
                              const float* __restrict__ gv,
                              float* __restrict__ gout)
{
    extern __shared__ __align__(16) float smem[];
    float*    tiles  = smem;                                 // [2][8192]
    float*    s_fx   = smem + 2 * HALF_FLOATS;               // [2][256]
    float*    s_fy   = s_fx + 2 * P_;                        // [2][256]
    uint16_t* s_off  = (uint16_t*)(s_fy + 2 * P_);           // [2][256]
    int*      s_next = (int*)(s_off + 2 * P_);               // [2]

    const int t   = threadIdx.x;
    const int bid = blockIdx.x;

    const uint32_t tile_sm0 =
        (uint32_t)__cvta_generic_to_shared(tiles) + t * 16u;
    const uint32_t tile_stride = (uint32_t)(HALF_FLOATS * 4);

    const int fq = (t & 7);           // feature quad 0..7 (4 floats)
    const int sl = (t >> 3);          // sample lane 0..31

    auto stage = [&](int w, int b) {
        const int c = w >> 1;
        const int h = w & 1;
        const float4* base4 = (const float4*)(gmap + (size_t)c * (H_ * W_ * F_));
        const uint32_t dst0 = tile_sm0 + (uint32_t)b * tile_stride;
        #pragma unroll
        for (int k = 0; k < HALF_CHUNKS / THREADS; ++k) {    // 8
            const int j    = k * THREADS + t;
            const int cell = j >> 3;
            const int wi   = j & 7;
            cp_async16(dst0 + k * (THREADS * 16u),
                       base4 + cell * (F_ / 4) + h * (FH_ / 4) + wi);
        }
    };

    auto params = [&](int w, int b) {
        const int c = w >> 1;
        const float uu = gu[(size_t)c * P_ + t];
        const float vv = gv[(size_t)c * P_ + t];
        const float x = uu * (float)(W_ - 1);
        const float y = vv * (float)(H_ - 1);
        int x0 = (int)floorf(x);
        int y0 = (int)floorf(y);
        x0 = min(max(x0, 0), W_ - 2);
        y0 = min(max(y0, 0), H_ - 2);
        s_fx[b * P_ + t]  = x - (float)x0;
        s_fy[b * P_ + t]  = y - (float)y0;
        s_off[b * P_ + t] = (uint16_t)((y0 * W_ + x0) * FH_);
    };

    // ---- prologue: item w0=bid -> buffer 0; steal successor into s_next[0]
    int w = bid;                       // bid < 444 < 4096: always valid
    stage(w, 0);
    cp_async_commit();
    params(w, 0);
    if (t == 0) s_next[0] = (int)atomicAdd(&g_ctr, 1u);
    __syncthreads();                   // publish s_next[0] (+ params irrelevant)

    // ---- persistent loop ----
    int b = 0;
    while (w < ITEMS) {
        // successor item (stolen last iteration / prologue)
        const int wn = s_next[b];

        // 1) stage successor into the other buffer (overlaps this compute)
        if (wn < ITEMS) {
            stage(wn, b ^ 1);
            params(wn, b ^ 1);
        }
        cp_async_commit();             // one group per iteration, always

        // 2) steal the item after that (published by the barrier below)
        if (t == 0) s_next[b ^ 1] = (int)atomicAdd(&g_ctr, 1u);

        // 3) current tile landed (non-blocking in steady state)
        cp_async_wait1();
        __syncthreads();

        // 4) bilinear gather (conflict-free 128B rows) + NT coalesced stores
        const int c = w >> 1;
        const int h = w & 1;
        const float*    tile = tiles + b * HALF_FLOATS;
        const uint16_t* off_ = s_off + b * P_;
        const float*    fx_  = s_fx + b * P_;
        const float*    fy_  = s_fy + b * P_;
        float4* out4 = (float4*)(gout + (size_t)c * P_ * F_) + h * (FH_ / 4);

        #pragma unroll
        for (int i = 0; i < P_ / 32; ++i) {            // 8 iterations
            const int s   = i * 32 + sl;
            const int off = (int)off_[s] + fq * 4;
            const float fx = fx_[s];
            const float fy = fy_[s];

            const float4 g00 = *(const float4*)(tile + off);
            const float4 g01 = *(const float4*)(tile + off + FH_);
            const float4 g10 = *(const float4*)(tile + off + W_ * FH_);
            const float4 g11 = *(const float4*)(tile + off + W_ * FH_ + FH_);

            const float w11 = fx * fy;
            const float w01 = fx - w11;               // fx*(1-fy)
            const float w10 = fy - w11;               // (1-fx)*fy
            const float w00 = 1.0f - fx - fy + w11;

            float4 r;
            r.x = g00.x * w00 + g01.x * w01 + g10.x * w10 + g11.x * w11;
            r.y = g00.y * w00 + g01.y * w01 + g10.y * w10 + g11.y * w11;
            r.z = g00.z * w00 + g01.z * w01 + g10.z * w10 + g11.z * w11;
            r.w = g00.w * w00 + g01.w * w01 + g10.w * w10 + g11.w * w11;

            __stcs(&out4[s * (F_ / 4) + fq], r);      // evict-first in L2
        }

        // 5) reads of tile[b]/params[b]/s_next[b] done before overwrite
        __syncthreads();
        w = wn;
        b ^= 1;
    }
}

extern "C" void kernel_launch(void* const* d_in, const int* in_sizes, int n_in,
                              void* d_out, int out_size)
{
    const float* gmap = (const float*)d_in[0];
    const float* gu   = (const float*)d_in[1];
    const float* gv   = (const float*)d_in[2];
    float* gout       = (float*)d_out;

    cudaFuncSetAttribute(ngf_texture_fetch_kernel,
                         cudaFuncAttributeMaxDynamicSharedMemorySize, SMEM_TOTAL);

    reset_ctr_kernel<<<1, 1>>>();
    ngf_texture_fetch_kernel<<<GRID, THREADS, SMEM_TOTAL>>>(gmap, gu, gv, gout);
}